// round 16
// baseline (speedup 1.0000x reference)
#include <cuda_runtime.h>
#include <cuda_fp16.h>
#include <math.h>
#include <stddef.h>
#include <stdint.h>

// ---------------------------------------------------------------------------
// Problem constants
// ---------------------------------------------------------------------------
#define Bn   16
#define NT   1025            // tokens (1 cls + 1024 patches)
#define Cd   768
#define Hh   12
#define Dd   64
#define NP   1024            // patch tokens
#define Ll   256             // landmarks (16x16)
#define BH   (Bn*Hh)         // 192
#define NEWTON_ITERS 6
#define NEG_INV_TAU (-0.125f)   // tau = sqrt(64) = 8

// ---------------------------------------------------------------------------
// Scratch (static device globals) — intermediates in fp16, norms in fp32
// ---------------------------------------------------------------------------
__device__ __align__(16) __half g_xh[(size_t)Bn * NT * Cd];   // fp16 copy of x
__device__ __align__(16) __half g_qkvwh[3 * Cd * Cd];         // fp16 qkv_w
__device__ __align__(16) __half g_projwh[Cd * Cd];            // fp16 proj_w
__device__ __align__(16) __half g_q[BH * NT * Dd];
__device__ __align__(16) __half g_k[BH * NT * Dd];
__device__ __align__(16) __half g_v[BH * NT * Dd];
__device__ __align__(16) __half g_qland[BH * Ll * Dd];
__device__ __align__(16) __half g_kland[BH * Ll * Dd];
__device__ float g_qpn[BH * NP];
__device__ float g_kpn[BH * NP];
__device__ float g_qln[BH * Ll];
__device__ float g_kln[BH * Ll];
__device__ float g_qcn[BH];
__device__ __align__(16) __half g_M2[(size_t)BH * Ll * Ll];
__device__ __align__(16) __half g_invA[(size_t)BH * Ll * Ll];
__device__ __align__(16) __half g_invB[(size_t)BH * Ll * Ll];
__device__ __align__(16) __half g_T[(size_t)BH * Ll * Ll];
__device__ __align__(16) __half g_KV[BH * Ll * Dd];
__device__ __align__(16) __half g_Vmix[BH * Ll * Dd];
__device__ __align__(16) __half g_attn[(size_t)Bn * NT * Cd];

// ---------------------------------------------------------------------------
// Fast exp on FMA/ALU pipes (no MUFU).
// ---------------------------------------------------------------------------
__device__ __forceinline__ float fast_exp(float x)
{
    float y  = x * 1.4426950408889634f;       // log2(e)
    int   ni = __float2int_rn(y);
    float nf = (float)ni;
    float f  = y - nf;                        // [-0.5, 0.5]
    float p = 1.3333558146e-3f;
    p = fmaf(p, f, 9.6181291076e-3f);
    p = fmaf(p, f, 5.5504108664e-2f);
    p = fmaf(p, f, 2.4022650696e-1f);
    p = fmaf(p, f, 6.9314718056e-1f);
    p = fmaf(p, f, 1.0f);
    return __int_as_float(__float_as_int(p) + (ni << 23));
}

// ---------------------------------------------------------------------------
// Epilogue functors (batched GEMM)
// ---------------------------------------------------------------------------
struct EpiQKV {
    const float* bias;
    __device__ __forceinline__ void store(int, int m, int j, float acc) const {
        int b = m / NT, n = m % NT;
        int part = j / Cd;
        int rem  = j % Cd;
        int h = rem / Dd, d = rem % Dd;
        __half* dst = (part == 0) ? g_q : ((part == 1) ? g_k : g_v);
        dst[(((size_t)b * Hh + h) * NT + n) * Dd + d] = __float2half_rn(acc + bias[j]);
    }
};

struct EpiGauss {
    const float* xn; const float* yn; __half* out;
    int sxn; int syn; int ldc; size_t sout;
    __device__ __forceinline__ void store(int bh, int m, int n, float acc) const {
        float dist = xn[(size_t)bh * sxn + m] + yn[(size_t)bh * syn + n] - 2.0f * acc;
        out[(size_t)bh * sout + (size_t)m * ldc + n] =
            __float2half_rn(fast_exp(dist * NEG_INV_TAU));
    }
};

struct EpiPlainH {
    __half* out; int ldc; size_t s;
    __device__ __forceinline__ void store(int bh, int m, int n, float acc) const {
        out[(size_t)bh * s + (size_t)m * ldc + n] = __float2half_rn(acc);
    }
};

struct EpiNewton {   // out = 2*inv - acc
    const __half* inv; __half* out;
    __device__ __forceinline__ void store(int bh, int m, int n, float acc) const {
        size_t off = ((size_t)bh * Ll + m) * Ll + n;
        out[off] = __float2half_rn(2.0f * __half2float(inv[off]) - acc);
    }
};

struct EpiProj {
    const float* bias; float* out;
    __device__ __forceinline__ void store(int, int m, int j, float acc) const {
        out[(size_t)m * Cd + j] = acc + bias[j];
    }
};

// Fused-kernel output functors
struct OutKV {
    __device__ __forceinline__ void store(int bh, int row, int d, float v) const {
        g_KV[((size_t)bh * Ll + row) * Dd + d] = __float2half_rn(v);
    }
};
struct OutYP {
    __device__ __forceinline__ void store(int bh, int row, int d, float v) const {
        int b = bh / Hh, h = bh % Hh;
        g_attn[((size_t)b * NT + row + 1) * Cd + h * Dd + d] = __float2half_rn(v);
    }
};

// ---------------------------------------------------------------------------
// fp16 MMA / cp.async helpers
// ---------------------------------------------------------------------------
__device__ __forceinline__ unsigned pack2h(float a, float b) {
    __half2 h = __floats2half2_rn(a, b);      // lo = a, hi = b
    return *(unsigned*)&h;
}

__device__ __forceinline__ void mma_f16(float* c, const unsigned* a, const unsigned* b) {
    asm volatile(
        "mma.sync.aligned.m16n8k16.row.col.f32.f16.f16.f32 "
        "{%0,%1,%2,%3}, {%4,%5,%6,%7}, {%8,%9}, {%0,%1,%2,%3};"
        : "+f"(c[0]), "+f"(c[1]), "+f"(c[2]), "+f"(c[3])
        : "r"(a[0]), "r"(a[1]), "r"(a[2]), "r"(a[3]), "r"(b[0]), "r"(b[1]));
}

__device__ __forceinline__ void ldsm4h(unsigned* r, const __half* p) {
    unsigned a = (unsigned)__cvta_generic_to_shared((void*)p);
    asm volatile("ldmatrix.sync.aligned.m8n8.x4.shared.b16 {%0,%1,%2,%3}, [%4];"
                 : "=r"(r[0]), "=r"(r[1]), "=r"(r[2]), "=r"(r[3]) : "r"(a));
}

__device__ __forceinline__ void ldsm4h_t(unsigned* r, const __half* p) {
    unsigned a = (unsigned)__cvta_generic_to_shared((void*)p);
    asm volatile("ldmatrix.sync.aligned.m8n8.x4.trans.shared.b16 {%0,%1,%2,%3}, [%4];"
                 : "=r"(r[0]), "=r"(r[1]), "=r"(r[2]), "=r"(r[3]) : "r"(a));
}

__device__ __forceinline__ void cpa16(__half* dst, const __half* src, bool valid) {
    unsigned d = (unsigned)__cvta_generic_to_shared((void*)dst);
    int sz = valid ? 16 : 0;
    asm volatile("cp.async.ca.shared.global [%0], [%1], 16, %2;"
                 :: "r"(d), "l"(src), "r"(sz));
}
#define CP_COMMIT() asm volatile("cp.async.commit_group;")
#define CP_WAIT1()  asm volatile("cp.async.wait_group 1;" ::: "memory")
#define CP_WAIT0()  asm volatile("cp.async.wait_group 0;" ::: "memory")

// ---------------------------------------------------------------------------
// Pipelined fp16 tensor-core GEMM (2-stage cp.async double buffering).
//   C = A(MxK, row-major, lda) @ op(B), all operands fp16.
//   BT=true : B is [N x K] row-major (C = A @ B^T)
//   BT=false: B is [K x N] row-major (C = A @ B)
// Requires: K % 32 == 0, Nn % BN == 0, lda/ldb % 8 == 0. M may be ragged.
// ---------------------------------------------------------------------------
template<int BM, int BN, bool BT, class Epi>
__global__ void __launch_bounds__((BM / 64) * (BN / 32) * 32)
gemm_tc(const __half* __restrict__ A, const __half* __restrict__ Bp,
        int M, int Nn, int K, int lda, int ldb,
        size_t sA, size_t sB, Epi epi)
{
    constexpr int BK = 32;
    constexpr int WARPS_M = BM / 64;
    constexpr int WARPS_N = BN / 32;
    constexpr int THREADS = WARPS_M * WARPS_N * 32;
    constexpr int SAH  = BK + 8;     // A / BT-B row stride (halfs): 80 B rows
    constexpr int SBNH = BN + 8;     // non-BT B row stride (halfs)
    constexpr int ASZ  = BM * SAH;
    constexpr int BSZ  = BT ? (BN * SAH) : (BK * SBNH);

    __shared__ __align__(16) __half As[2 * ASZ];
    __shared__ __align__(16) __half Bs[2 * BSZ];

    const int bh = blockIdx.z;
    A  += (size_t)bh * sA;
    Bp += (size_t)bh * sB;
    const int m0 = blockIdx.y * BM;
    const int n0 = blockIdx.x * BN;
    const int tid  = threadIdx.x;
    const int lane = tid & 31;
    const int warp = tid >> 5;
    const int wm = warp / WARPS_N;
    const int wn = warp % WARPS_N;
    const int gid = lane >> 2;      // 0..7
    const int tig = lane & 3;       // 0..3
    const int rr  = lane & 7;       // ldmatrix row within 8-group
    const int sub = lane >> 3;      // ldmatrix sub-matrix id 0..3

    float acc[4][4][4];
#pragma unroll
    for (int i = 0; i < 4; i++)
#pragma unroll
        for (int j = 0; j < 4; j++)
#pragma unroll
            for (int r = 0; r < 4; r++) acc[i][j][r] = 0.0f;

    // ---- async tile loader (16B = 8 halfs per cp.async) ----
    auto load_tile = [&](int k0, int s) {
        __half* Asb = As + s * ASZ;
        __half* Bsb = Bs + s * BSZ;
#pragma unroll
        for (int t = 0; t < (BM * 4) / THREADS; t++) {
            int i = tid + t * THREADS;
            int m = i >> 2;             // 4 chunks of 8 halfs per row
            int q = i & 3;
            bool v = (m0 + m < M);
            const __half* src = A + (size_t)(v ? (m0 + m) : m0) * lda + k0 + q * 8;
            cpa16(&Asb[m * SAH + q * 8], src, v);
        }
        if (BT) {
#pragma unroll
            for (int t = 0; t < (BN * 4) / THREADS; t++) {
                int i = tid + t * THREADS;
                int n = i >> 2;
                int q = i & 3;
                cpa16(&Bsb[n * SAH + q * 8],
                      Bp + (size_t)(n0 + n) * ldb + k0 + q * 8, true);
            }
        } else {
#pragma unroll
            for (int t = 0; t < (BK * BN / 8) / THREADS; t++) {
                int i  = tid + t * THREADS;
                int kk = i / (BN / 8);
                int nq = i % (BN / 8);
                cpa16(&Bsb[kk * SBNH + nq * 8],
                      Bp + (size_t)(k0 + kk) * ldb + n0 + nq * 8, true);
            }
        }
        CP_COMMIT();
    };

    const int nk = K / BK;
    load_tile(0, 0);

    for (int it = 0; it < nk; it++) {
        const int s = it & 1;
        if (it + 1 < nk) {
            load_tile((it + 1) * BK, s ^ 1);
            CP_WAIT1();                 // stage s complete; s^1 in flight
        } else {
            CP_WAIT0();
        }
        __syncthreads();

        const __half* Asb = As + s * ASZ;
        const __half* Bsb = Bs + s * BSZ;
#pragma unroll
        for (int kk = 0; kk < BK; kk += 16) {
            unsigned af[4][4], bf[4][2];
            {
                int arow = rr + (sub & 1) * 8;
                int acol = kk + (sub >> 1) * 8;
#pragma unroll
                for (int i = 0; i < 4; i++) {
                    int row = wm * 64 + i * 16 + arow;
                    ldsm4h(af[i], &Asb[row * SAH + acol]);
                }
            }
            if (BT) {
                int brow = rr + (sub & 1) * 8;
                int bcol = kk + (sub >> 1) * 8;
#pragma unroll
                for (int jp = 0; jp < 2; jp++) {
                    int n = wn * 32 + jp * 16 + brow;
                    unsigned tmp[4];
                    ldsm4h(tmp, &Bsb[n * SAH + bcol]);
                    bf[jp * 2][0]     = tmp[0];
                    bf[jp * 2][1]     = tmp[2];
                    bf[jp * 2 + 1][0] = tmp[1];
                    bf[jp * 2 + 1][1] = tmp[3];
                }
            } else {
                int krow = kk + (sub & 1) * 8 + rr;
#pragma unroll
                for (int jp = 0; jp < 2; jp++) {
                    int ncol = wn * 32 + jp * 16 + (sub >> 1) * 8;
                    unsigned tmp[4];
                    ldsm4h_t(tmp, &Bsb[krow * SBNH + ncol]);
                    bf[jp * 2][0]     = tmp[0];
                    bf[jp * 2][1]     = tmp[1];
                    bf[jp * 2 + 1][0] = tmp[2];
                    bf[jp * 2 + 1][1] = tmp[3];
                }
            }
#pragma unroll
            for (int i = 0; i < 4; i++)
#pragma unroll
                for (int j = 0; j < 4; j++)
                    mma_f16(acc[i][j], af[i], bf[j]);
        }
        __syncthreads();   // stage s reads done before it+1 overwrites it
    }

    // ---- epilogue (N exact multiple of BN; only M ragged) ----
#pragma unroll
    for (int i = 0; i < 4; i++) {
        int rm = m0 + wm * 64 + i * 16 + gid;
#pragma unroll
        for (int j = 0; j < 4; j++) {
            int cn = n0 + wn * 32 + j * 8 + tig * 2;
            if (rm < M) {
                epi.store(bh, rm, cn,     acc[i][j][0]);
                epi.store(bh, rm, cn + 1, acc[i][j][1]);
            }
            if (rm + 8 < M) {
                epi.store(bh, rm + 8, cn,     acc[i][j][2]);
                epi.store(bh, rm + 8, cn + 1, acc[i][j][3]);
            }
        }
    }
}

// ---------------------------------------------------------------------------
// Fused gauss + AV kernel (R15, unchanged).
// ---------------------------------------------------------------------------
#define FUSED_SMEM (2 * 128 * 72 * 2 + 128 * 136 * 2)   // Aq + Bs + Ps = 71680 B

template<class Out>
__global__ void __launch_bounds__(256)
fused_gauss_av(const __half* __restrict__ Abase,
               const __half* __restrict__ Bbase,
               const __half* __restrict__ Vbase,
               const float* __restrict__ xn, const float* __restrict__ yn,
               int nxs, int nys,
               size_t sA, size_t sB, size_t sV,
               int ntiles, Out out)
{
    constexpr int SAH = 72;
    constexpr int SPH = 136;
    extern __shared__ __half fsm[];
    __half* Aq = fsm;
    __half* Bs = Aq + 128 * SAH;
    __half* Ps = Bs + 128 * SAH;

    const int bh    = blockIdx.y;
    const int arow0 = blockIdx.x * 128;
    const int tid  = threadIdx.x;
    const int lane = tid & 31;
    const int warp = tid >> 5;
    const int wm = warp >> 2;
    const int wn = warp & 3;
    const int gid = lane >> 2;
    const int tig = lane & 3;
    const int rr  = lane & 7;
    const int sub = lane >> 3;

    const __half* Ag = Abase + (size_t)bh * sA + (size_t)arow0 * Dd;
    const __half* Bg = Bbase + (size_t)bh * sB;
    const __half* Vg = Vbase + (size_t)bh * sV;
    const float* xnb = xn + (size_t)bh * nxs + arow0;
    const float* ynb = yn + (size_t)bh * nys;

#pragma unroll
    for (int t = 0; t < 8; ++t) {
        int i = tid + t * 256;
        int r = i >> 4;
        int q = i & 15;
        *(uint2*)&Aq[r * SAH + q * 4] = *(const uint2*)&Ag[(size_t)r * Dd + q * 4];
    }

    float accY[4][2][4];
#pragma unroll
    for (int i = 0; i < 4; i++)
#pragma unroll
        for (int j = 0; j < 2; j++)
#pragma unroll
            for (int r = 0; r < 4; r++) accY[i][j][r] = 0.0f;

    for (int t = 0; t < ntiles; ++t) {
        __syncthreads();
#pragma unroll
        for (int u = 0; u < 8; ++u) {
            int i = tid + u * 256;
            int r = i >> 4, q = i & 15;
            *(uint2*)&Bs[r * SAH + q * 4] =
                *(const uint2*)&Bg[(size_t)(t * 128 + r) * Dd + q * 4];
        }
        __syncthreads();

#pragma unroll
        for (int nh = 0; nh < 2; ++nh) {
            float acc[4][2][4];
#pragma unroll
            for (int i = 0; i < 4; i++)
#pragma unroll
                for (int j = 0; j < 2; j++)
#pragma unroll
                    for (int r = 0; r < 4; r++) acc[i][j][r] = 0.0f;

#pragma unroll
            for (int kk = 0; kk < 64; kk += 16) {
                unsigned af[4][4], bf[2][2];
                int arow = rr + (sub & 1) * 8;
                int acol = kk + (sub >> 1) * 8;
#pragma unroll
                for (int i = 0; i < 4; i++)
                    ldsm4h(af[i], &Aq[(wm * 64 + i * 16 + arow) * SAH + acol]);
                int brow = nh * 64 + wn * 16 + rr + (sub & 1) * 8;
                int bcol = kk + (sub >> 1) * 8;
                unsigned tmp[4];
                ldsm4h(tmp, &Bs[brow * SAH + bcol]);
                bf[0][0] = tmp[0]; bf[0][1] = tmp[2];
                bf[1][0] = tmp[1]; bf[1][1] = tmp[3];
#pragma unroll
                for (int i = 0; i < 4; i++)
#pragma unroll
                    for (int j = 0; j < 2; j++)
                        mma_f16(acc[i][j], af[i], bf[j]);
            }
#pragma unroll
            for (int i = 0; i < 4; i++) {
                int rm = wm * 64 + i * 16 + gid;
                float xa = xnb[rm];
                float xb = xnb[rm + 8];
#pragma unroll
                for (int j = 0; j < 2; j++) {
                    int cn = nh * 64 + wn * 16 + j * 8 + tig * 2;
                    float y0 = ynb[t * 128 + cn];
                    float y1 = ynb[t * 128 + cn + 1];
                    float e0 = fast_exp((xa + y0 - 2.0f * acc[i][j][0]) * NEG_INV_TAU);
                    float e1 = fast_exp((xa + y1 - 2.0f * acc[i][j][1]) * NEG_INV_TAU);
                    float e2 = fast_exp((xb + y0 - 2.0f * acc[i][j][2]) * NEG_INV_TAU);
                    float e3 = fast_exp((xb + y1 - 2.0f * acc[i][j][3]) * NEG_INV_TAU);
                    *(__half2*)&Ps[rm * SPH + cn]       = __floats2half2_rn(e0, e1);
                    *(__half2*)&Ps[(rm + 8) * SPH + cn] = __floats2half2_rn(e2, e3);
                }
            }
        }
        __syncthreads();

#pragma unroll
        for (int u = 0; u < 8; ++u) {
            int i = tid + u * 256;
            int r = i >> 4, q = i & 15;
            *(uint2*)&Bs[r * SAH + q * 4] =
                *(const uint2*)&Vg[(size_t)(t * 128 + r) * Dd + q * 4];
        }
        __syncthreads();

#pragma unroll
        for (int kk = 0; kk < 128; kk += 16) {
            unsigned af[4][4], bf[2][2];
            int arow = rr + (sub & 1) * 8;
            int acol = kk + (sub >> 1) * 8;
#pragma unroll
            for (int i = 0; i < 4; i++)
                ldsm4h(af[i], &Ps[(wm * 64 + i * 16 + arow) * SPH + acol]);
            int krow = kk + (sub & 1) * 8 + rr;
            int ncol = wn * 16 + (sub >> 1) * 8;
            unsigned tmp[4];
            ldsm4h_t(tmp, &Bs[krow * SAH + ncol]);
            bf[0][0] = tmp[0]; bf[0][1] = tmp[1];
            bf[1][0] = tmp[2]; bf[1][1] = tmp[3];
#pragma unroll
            for (int i = 0; i < 4; i++)
#pragma unroll
                for (int j = 0; j < 2; j++)
                    mma_f16(accY[i][j], af[i], bf[j]);
        }
    }

#pragma unroll
    for (int i = 0; i < 4; i++) {
        int rm = wm * 64 + i * 16 + gid;
#pragma unroll
        for (int j = 0; j < 2; j++) {
            int cn = wn * 16 + j * 8 + tig * 2;
            out.store(bh, arow0 + rm,     cn,     accY[i][j][0]);
            out.store(bh, arow0 + rm,     cn + 1, accY[i][j][1]);
            out.store(bh, arow0 + rm + 8, cn,     accY[i][j][2]);
            out.store(bh, arow0 + rm + 8, cn + 1, accY[i][j][3]);
        }
    }
}

// ---------------------------------------------------------------------------
// Small helper kernels
// ---------------------------------------------------------------------------
__global__ void cvt_fp16_kernel(const float* __restrict__ src,
                                __half* __restrict__ dst, int n)
{
    int i = (blockIdx.x * blockDim.x + threadIdx.x) * 4;
    if (i >= n) return;
    float4 v = *(const float4*)&src[i];
    uint2 u = make_uint2(pack2h(v.x, v.y), pack2h(v.z, v.w));
    *(uint2*)&dst[i] = u;
}

__global__ void pool_kernel()
{
    int idx = blockIdx.x * blockDim.x + threadIdx.x;
    if (idx >= BH * Ll * Dd) return;
    int d  = idx % Dd;
    int l  = (idx / Dd) % Ll;
    int bh = idx / (Dd * Ll);
    int lr = l / 16, lc = l % 16;
    float sq = 0.f, sk = 0.f;
#pragma unroll
    for (int r = 0; r < 2; r++)
#pragma unroll
        for (int c = 0; c < 2; c++) {
            int p = (2 * lr + r) * 32 + (2 * lc + c);
            size_t off = ((size_t)bh * NT + (p + 1)) * Dd + d;
            sq += __half2float(g_q[off]);
            sk += __half2float(g_k[off]);
        }
    g_qland[((size_t)bh * Ll + l) * Dd + d] = __float2half_rn(sq * 0.25f);
    g_kland[((size_t)bh * Ll + l) * Dd + d] = __float2half_rn(sk * 0.25f);
}

__device__ __forceinline__ float row_sq_norm_h(const __half* p)
{
    const __half2* p2 = (const __half2*)p;
    float s = 0.f;
#pragma unroll
    for (int i = 0; i < Dd / 2; i++) {
        float2 v = __half22float2(p2[i]);
        s += v.x * v.x + v.y * v.y;
    }
    return s;
}

__global__ void norms_patch_kernel()
{
    int idx = blockIdx.x * blockDim.x + threadIdx.x;
    if (idx >= BH * NP) return;
    int bh = idx / NP, p = idx % NP;
    size_t off = ((size_t)bh * NT + (p + 1)) * Dd;
    g_qpn[idx] = row_sq_norm_h(&g_q[off]);
    g_kpn[idx] = row_sq_norm_h(&g_k[off]);
}

__global__ void norms_land_kernel()
{
    int idx = blockIdx.x * blockDim.x + threadIdx.x;
    if (idx >= BH * Ll) return;
    g_qln[idx] = row_sq_norm_h(&g_qland[(size_t)idx * Dd]);
    g_kln[idx] = row_sq_norm_h(&g_kland[(size_t)idx * Dd]);
    if (idx < BH)
        g_qcn[idx] = row_sq_norm_h(&g_q[(size_t)idx * NT * Dd]);  // n = 0 (cls)
}

__global__ void newton_init_kernel()
{
    int bh = blockIdx.x;
    int t  = threadIdx.x;
    const __half* M2b = g_M2 + (size_t)bh * Ll * Ll;
    const __half* row = M2b + (size_t)t * Ll;
    float rs = 0.f;
    for (int j = 0; j < Ll; j++) rs += fabsf(__half2float(row[j]));
    __shared__ float red[256];
    red[t] = rs;
    __syncthreads();
    for (int s = 128; s > 0; s >>= 1) {
        if (t < s) red[t] = fmaxf(red[t], red[t + s]);
        __syncthreads();
    }
    float nrm = red[0];
    float scale = 1.0f / (nrm * nrm + 1e-6f);
    __half* inv = g_invA + (size_t)bh * Ll * Ll;
    for (int idx = t; idx < Ll * Ll; idx += 256) {
        int i = idx / Ll, j = idx % Ll;
        inv[idx] = __float2half_rn(__half2float(M2b[(size_t)j * Ll + i]) * scale);
    }
}

__global__ void ycls_kernel()
{
    int bh = blockIdx.x;
    int t  = threadIdx.x;
    __shared__ float sc[Ll];
    __shared__ float qc[Dd];
    if (t < Dd) qc[t] = __half2float(g_q[(size_t)bh * NT * Dd + t]);
    __syncthreads();
    const __half* kl = g_kland + ((size_t)bh * Ll + t) * Dd;
    float dot = 0.f;
#pragma unroll
    for (int d = 0; d < Dd; d++) dot += qc[d] * __half2float(kl[d]);
    float dist = g_qcn[bh] + g_kln[(size_t)bh * Ll + t] - 2.0f * dot;
    sc[t] = fast_exp(dist * NEG_INV_TAU);
    __syncthreads();
    if (t < Dd) {
        float s = 0.f;
        for (int l = 0; l < Ll; l++)
            s += sc[l] * __half2float(g_Vmix[((size_t)bh * Ll + l) * Dd + t]);
        int b = bh / Hh, h = bh % Hh;
        g_attn[(size_t)b * NT * Cd + h * Dd + t] = __float2half_rn(s);
    }
}

// ---------------------------------------------------------------------------
// Host launchers
// ---------------------------------------------------------------------------
template<int BM, int BN, bool BT, class Epi>
static void launch_gemm(dim3 grid, const __half* A, const __half* Bp,
                        int M, int Nn, int K, int lda, int ldb,
                        size_t sA, size_t sB, Epi epi)
{
    constexpr int THREADS = (BM / 64) * (BN / 32) * 32;
    gemm_tc<BM, BN, BT, Epi><<<grid, THREADS>>>(
        A, Bp, M, Nn, K, lda, ldb, sA, sB, epi);
}

template<class Out>
static void launch_fused(dim3 grid, const __half* A, const __half* B, const __half* V,
                         const float* xn, const float* yn, int nxs, int nys,
                         size_t sA, size_t sB, size_t sV, int ntiles, Out out)
{
    static bool attr_done = false;
    if (!attr_done) {
        cudaFuncSetAttribute((const void*)fused_gauss_av<Out>,
                             cudaFuncAttributeMaxDynamicSharedMemorySize, FUSED_SMEM);
        attr_done = true;
    }
    fused_gauss_av<Out><<<grid, 256, FUSED_SMEM>>>(
        A, B, V, xn, yn, nxs, nys, sA, sB, sV, ntiles, out);
}

extern "C" void kernel_launch(void* const* d_in, const int* in_sizes, int n_in,
                              void* d_out, int out_size)
{
    (void)in_sizes; (void)n_in; (void)out_size;
    const float* x      = (const float*)d_in[0];
    const float* qkv_w  = (const float*)d_in[1];
    const float* qkv_b  = (const float*)d_in[2];
    const float* proj_w = (const float*)d_in[3];
    const float* proj_b = (const float*)d_in[4];
    float* out = (float*)d_out;

    __half *p_xh, *p_qkvwh, *p_projwh;
    __half *p_q, *p_k, *p_v, *p_qland, *p_kland;
    float *p_qpn, *p_kpn, *p_qln, *p_kln;
    __half *p_M2, *p_invA, *p_invB, *p_T, *p_KV, *p_Vmix, *p_attn;
    cudaGetSymbolAddress((void**)&p_xh, g_xh);
    cudaGetSymbolAddress((void**)&p_qkvwh, g_qkvwh);
    cudaGetSymbolAddress((void**)&p_projwh, g_projwh);
    cudaGetSymbolAddress((void**)&p_q, g_q);
    cudaGetSymbolAddress((void**)&p_k, g_k);
    cudaGetSymbolAddress((void**)&p_v, g_v);
    cudaGetSymbolAddress((void**)&p_qland, g_qland);
    cudaGetSymbolAddress((void**)&p_kland, g_kland);
    cudaGetSymbolAddress((void**)&p_qpn, g_qpn);
    cudaGetSymbolAddress((void**)&p_kpn, g_kpn);
    cudaGetSymbolAddress((void**)&p_qln, g_qln);
    cudaGetSymbolAddress((void**)&p_kln, g_kln);
    cudaGetSymbolAddress((void**)&p_M2, g_M2);
    cudaGetSymbolAddress((void**)&p_invA, g_invA);
    cudaGetSymbolAddress((void**)&p_invB, g_invB);
    cudaGetSymbolAddress((void**)&p_T, g_T);
    cudaGetSymbolAddress((void**)&p_KV, g_KV);
    cudaGetSymbolAddress((void**)&p_Vmix, g_Vmix);
    cudaGetSymbolAddress((void**)&p_attn, g_attn);

    const int M_tok = Bn * NT;   // 16400
    const int gy_tok = (M_tok + 127) / 128;

    // 0. pre-convert fp32 inputs to fp16
    {
        int nx = Bn * NT * Cd;          // 12,595,200
        int nw = 3 * Cd * Cd;           // 1,769,472
        int np = Cd * Cd;               // 589,824
        cvt_fp16_kernel<<<(nx / 4 + 255) / 256, 256>>>(x, p_xh, nx);
        cvt_fp16_kernel<<<(nw / 4 + 255) / 256, 256>>>(qkv_w, p_qkvwh, nw);
        cvt_fp16_kernel<<<(np / 4 + 255) / 256, 256>>>(proj_w, p_projwh, np);
    }

    // 1. QKV projection (fp16 x @ fp16 w^T)
    launch_gemm<128, 128, true>(dim3(3 * Cd / 128, gy_tok, 1),
        p_xh, p_qkvwh, M_tok, 3 * Cd, Cd, Cd, Cd, (size_t)0, (size_t)0,
        EpiQKV{qkv_b});

    // 2. pooling + norms
    pool_kernel<<<(BH * Ll * Dd + 255) / 256, 256>>>();
    norms_patch_kernel<<<(BH * NP + 255) / 256, 256>>>();
    norms_land_kernel<<<(BH * Ll + 255) / 256, 256>>>();

    // 3. M2 gauss (needed for Newton)
    launch_gemm<128, 128, true>(dim3(Ll / 128, Ll / 128, BH),
        p_qland, p_kland, Ll, Ll, Dd, Dd, Dd,
        (size_t)Ll * Dd, (size_t)Ll * Dd,
        EpiGauss{p_qln, p_kln, p_M2, Ll, Ll, Ll, (size_t)Ll * Ll});

    // 4. fused M3+KV: KV = gauss(q_land, k_patch) @ v_patch
    launch_fused(dim3(2, BH), p_qland, p_k + Dd, p_v + Dd,
                 p_qln, p_kpn, Ll, NP,
                 (size_t)Ll * Dd, (size_t)NT * Dd, (size_t)NT * Dd, NP / 128, OutKV{});

    // 5. Newton iterations for M2^-1
    newton_init_kernel<<<BH, 256>>>();
    {
        __half* cur = p_invA;
        __half* nxt = p_invB;
        dim3 grid(Ll / 128, Ll / 128, BH);
        for (int it = 0; it < NEWTON_ITERS; it++) {
            launch_gemm<128, 128, false>(grid,
                p_M2, (const __half*)cur, Ll, Ll, Ll, Ll, Ll,
                (size_t)Ll * Ll, (size_t)Ll * Ll,
                EpiPlainH{p_T, Ll, (size_t)Ll * Ll});
            launch_gemm<128, 128, false>(grid,
                (const __half*)cur, p_T, Ll, Ll, Ll, Ll, Ll,
                (size_t)Ll * Ll, (size_t)Ll * Ll,
                EpiNewton{cur, nxt});
            __half* tmp = cur; cur = nxt; nxt = tmp;
        }
        // NEWTON_ITERS even -> result in p_invA
    }

    // 6. V_mixed = M2_inv @ KV : [L x D]
    launch_gemm<128, 64, false>(dim3(1, Ll / 128, BH),
        (const __half*)p_invA, p_KV, Ll, Dd, Ll, Ll, Dd,
        (size_t)Ll * Ll, (size_t)Ll * Dd,
        EpiPlainH{p_Vmix, Dd, (size_t)Ll * Dd});

    // 7. fused M1+y_patch: attn_patch = gauss(q_patch, k_land) @ V_mixed
    launch_fused(dim3(NP / 128, BH), p_q + Dd, p_kland, p_Vmix,
                 p_qpn, p_kln, NP, Ll,
                 (size_t)NT * Dd, (size_t)Ll * Dd, (size_t)Ll * Dd, Ll / 128, OutYP{});

    // 8. y_cls
    ycls_kernel<<<BH, 256>>>();

    // 9. output projection (fp16 attn @ fp16 w^T, fp32 out)
    launch_gemm<128, 128, true>(dim3(Cd / 128, gy_tok, 1),
        (const __half*)p_attn, p_projwh, M_tok, Cd, Cd, Cd, Cd,
        (size_t)0, (size_t)0, EpiProj{proj_b, out});
}

// round 17
// speedup vs baseline: 1.4218x; 1.4218x over previous
#include <cuda_runtime.h>
#include <cuda_fp16.h>
#include <math.h>
#include <stddef.h>
#include <stdint.h>

// ---------------------------------------------------------------------------
// Problem constants
// ---------------------------------------------------------------------------
#define Bn   16
#define NT   1025            // tokens (1 cls + 1024 patches)
#define Cd   768
#define Hh   12
#define Dd   64
#define NP   1024            // patch tokens
#define Ll   256             // landmarks (16x16)
#define BH   (Bn*Hh)         // 192
#define NEWTON_ITERS 6
#define NEG_INV_TAU (-0.125f)   // tau = sqrt(64) = 8

// ---------------------------------------------------------------------------
// Scratch (static device globals) — intermediates in fp16, norms in fp32
// ---------------------------------------------------------------------------
__device__ __align__(16) __half g_xh[(size_t)Bn * NT * Cd];   // fp16 copy of x
__device__ __align__(16) __half g_qkvwh[3 * Cd * Cd];         // fp16 qkv_w
__device__ __align__(16) __half g_projwh[Cd * Cd];            // fp16 proj_w
__device__ __align__(16) __half g_q[BH * NT * Dd];
__device__ __align__(16) __half g_k[BH * NT * Dd];
__device__ __align__(16) __half g_v[BH * NT * Dd];
__device__ __align__(16) __half g_qland[BH * Ll * Dd];
__device__ __align__(16) __half g_kland[BH * Ll * Dd];
__device__ float g_qpn[BH * NP];
__device__ float g_kpn[BH * NP];
__device__ float g_qln[BH * Ll];
__device__ float g_kln[BH * Ll];
__device__ float g_qcn[BH];
__device__ __align__(16) __half g_M2[(size_t)BH * Ll * Ll];
__device__ __align__(16) __half g_invA[(size_t)BH * Ll * Ll];
__device__ __align__(16) __half g_invB[(size_t)BH * Ll * Ll];
__device__ __align__(16) __half g_T[(size_t)BH * Ll * Ll];
__device__ __align__(16) __half g_KV[BH * Ll * Dd];
__device__ __align__(16) __half g_Vmix[BH * Ll * Dd];
__device__ __align__(16) __half g_attn[(size_t)Bn * NT * Cd];

// ---------------------------------------------------------------------------
// Fast exp on FMA/ALU pipes (no MUFU).
// ---------------------------------------------------------------------------
__device__ __forceinline__ float fast_exp(float x)
{
    float y  = x * 1.4426950408889634f;       // log2(e)
    int   ni = __float2int_rn(y);
    float nf = (float)ni;
    float f  = y - nf;                        // [-0.5, 0.5]
    float p = 1.3333558146e-3f;
    p = fmaf(p, f, 9.6181291076e-3f);
    p = fmaf(p, f, 5.5504108664e-2f);
    p = fmaf(p, f, 2.4022650696e-1f);
    p = fmaf(p, f, 6.9314718056e-1f);
    p = fmaf(p, f, 1.0f);
    return __int_as_float(__float_as_int(p) + (ni << 23));
}

// ---------------------------------------------------------------------------
// Epilogue functors (batched GEMM)
// ---------------------------------------------------------------------------
struct EpiQKV {
    const float* bias;
    __device__ __forceinline__ void store(int, int m, int j, float acc) const {
        int b = m / NT, n = m % NT;
        int part = j / Cd;
        int rem  = j % Cd;
        int h = rem / Dd, d = rem % Dd;
        __half* dst = (part == 0) ? g_q : ((part == 1) ? g_k : g_v);
        dst[(((size_t)b * Hh + h) * NT + n) * Dd + d] = __float2half_rn(acc + bias[j]);
    }
};

struct EpiGauss {
    const float* xn; const float* yn; __half* out;
    int sxn; int syn; int ldc; size_t sout;
    __device__ __forceinline__ void store(int bh, int m, int n, float acc) const {
        float dist = xn[(size_t)bh * sxn + m] + yn[(size_t)bh * syn + n] - 2.0f * acc;
        out[(size_t)bh * sout + (size_t)m * ldc + n] =
            __float2half_rn(fast_exp(dist * NEG_INV_TAU));
    }
};

struct EpiPlainH {
    __half* out; int ldc; size_t s;
    __device__ __forceinline__ void store(int bh, int m, int n, float acc) const {
        out[(size_t)bh * s + (size_t)m * ldc + n] = __float2half_rn(acc);
    }
};

struct EpiNewton {   // out = 2*inv - acc
    const __half* inv; __half* out;
    __device__ __forceinline__ void store(int bh, int m, int n, float acc) const {
        size_t off = ((size_t)bh * Ll + m) * Ll + n;
        out[off] = __float2half_rn(2.0f * __half2float(inv[off]) - acc);
    }
};

struct EpiProj {
    const float* bias; float* out;
    __device__ __forceinline__ void store(int, int m, int j, float acc) const {
        out[(size_t)m * Cd + j] = acc + bias[j];
    }
};

// Fused-kernel output functors
struct OutKV {
    __device__ __forceinline__ void store(int bh, int row, int d, float v) const {
        g_KV[((size_t)bh * Ll + row) * Dd + d] = __float2half_rn(v);
    }
};
struct OutYP {
    __device__ __forceinline__ void store(int bh, int row, int d, float v) const {
        int b = bh / Hh, h = bh % Hh;
        g_attn[((size_t)b * NT + row + 1) * Cd + h * Dd + d] = __float2half_rn(v);
    }
};

// ---------------------------------------------------------------------------
// fp16 MMA helpers
// ---------------------------------------------------------------------------
__device__ __forceinline__ unsigned pack2h(float a, float b) {
    __half2 h = __floats2half2_rn(a, b);      // lo = a, hi = b
    return *(unsigned*)&h;
}

__device__ __forceinline__ void mma_f16(float* c, const unsigned* a, const unsigned* b) {
    asm volatile(
        "mma.sync.aligned.m16n8k16.row.col.f32.f16.f16.f32 "
        "{%0,%1,%2,%3}, {%4,%5,%6,%7}, {%8,%9}, {%0,%1,%2,%3};"
        : "+f"(c[0]), "+f"(c[1]), "+f"(c[2]), "+f"(c[3])
        : "r"(a[0]), "r"(a[1]), "r"(a[2]), "r"(a[3]), "r"(b[0]), "r"(b[1]));
}

__device__ __forceinline__ void ldsm4h(unsigned* r, const __half* p) {
    unsigned a = (unsigned)__cvta_generic_to_shared((void*)p);
    asm volatile("ldmatrix.sync.aligned.m8n8.x4.shared.b16 {%0,%1,%2,%3}, [%4];"
                 : "=r"(r[0]), "=r"(r[1]), "=r"(r[2]), "=r"(r[3]) : "r"(a));
}

__device__ __forceinline__ void ldsm4h_t(unsigned* r, const __half* p) {
    unsigned a = (unsigned)__cvta_generic_to_shared((void*)p);
    asm volatile("ldmatrix.sync.aligned.m8n8.x4.trans.shared.b16 {%0,%1,%2,%3}, [%4];"
                 : "=r"(r[0]), "=r"(r[1]), "=r"(r[2]), "=r"(r[3]) : "r"(a));
}

// ---------------------------------------------------------------------------
// Synchronous fp16 tensor-core GEMM (R15 structure, 16-byte loader).
//   C = A(MxK, row-major, lda) @ op(B), all operands fp16.
//   BT=true : B is [N x K] row-major (C = A @ B^T)
//   BT=false: B is [K x N] row-major (C = A @ B)
// Requires: K % 32 == 0, Nn % BN == 0, lda/ldb % 8 == 0. M may be ragged.
// ---------------------------------------------------------------------------
template<int BM, int BN, bool BT, class Epi>
__global__ void __launch_bounds__((BM / 64) * (BN / 32) * 32)
gemm_tc(const __half* __restrict__ A, const __half* __restrict__ Bp,
        int M, int Nn, int K, int lda, int ldb,
        size_t sA, size_t sB, Epi epi)
{
    constexpr int BK = 32;
    constexpr int WARPS_M = BM / 64;
    constexpr int WARPS_N = BN / 32;
    constexpr int THREADS = WARPS_M * WARPS_N * 32;
    constexpr int SAH  = BK + 8;     // A / BT-B row stride (halfs): 80 B rows
    constexpr int SBNH = BN + 8;     // non-BT B row stride (halfs): 272 B rows

    __shared__ __align__(16) __half As[BM * SAH];
    __shared__ __align__(16) __half Bs[BT ? (BN * SAH) : (BK * SBNH)];

    const int bh = blockIdx.z;
    A  += (size_t)bh * sA;
    Bp += (size_t)bh * sB;
    const int m0 = blockIdx.y * BM;
    const int n0 = blockIdx.x * BN;
    const int tid  = threadIdx.x;
    const int lane = tid & 31;
    const int warp = tid >> 5;
    const int wm = warp / WARPS_N;
    const int wn = warp % WARPS_N;
    const int gid = lane >> 2;      // 0..7
    const int tig = lane & 3;       // 0..3
    const int rr  = lane & 7;       // ldmatrix row within 8-group
    const int sub = lane >> 3;      // ldmatrix sub-matrix id 0..3

    float acc[4][4][4];
#pragma unroll
    for (int i = 0; i < 4; i++)
#pragma unroll
        for (int j = 0; j < 4; j++)
#pragma unroll
            for (int r = 0; r < 4; r++) acc[i][j][r] = 0.0f;

    for (int k0 = 0; k0 < K; k0 += BK) {
        // ---- A tile -> As[m][k] (16B chunks: 4 per row of BK=32 halfs) ----
#pragma unroll
        for (int t = 0; t < (BM * 4) / THREADS; t++) {
            int i = tid + t * THREADS;
            int m = i >> 2;
            int q = i & 3;
            uint4 u = make_uint4(0u, 0u, 0u, 0u);
            if (m0 + m < M)
                u = *(const uint4*)&A[(size_t)(m0 + m) * lda + k0 + q * 8];
            *(uint4*)&As[m * SAH + q * 8] = u;
        }
        // ---- B tile ----
        if (BT) {   // B [N x K] -> Bs[n][k]
#pragma unroll
            for (int t = 0; t < (BN * 4) / THREADS; t++) {
                int i = tid + t * THREADS;
                int n = i >> 2;
                int q = i & 3;
                *(uint4*)&Bs[n * SAH + q * 8] =
                    *(const uint4*)&Bp[(size_t)(n0 + n) * ldb + k0 + q * 8];
            }
        } else {    // B [K x N] -> Bs[k][n]
#pragma unroll
            for (int t = 0; t < (BK * BN / 8) / THREADS; t++) {
                int i  = tid + t * THREADS;
                int kk = i / (BN / 8);
                int nq = i % (BN / 8);
                *(uint4*)&Bs[kk * SBNH + nq * 8] =
                    *(const uint4*)&Bp[(size_t)(k0 + kk) * ldb + n0 + nq * 8];
            }
        }
        __syncthreads();

        // ---- compute: 2 x k16 steps per BK=32 ----
#pragma unroll
        for (int kk = 0; kk < BK; kk += 16) {
            unsigned af[4][4], bf[4][2];
            {
                int arow = rr + (sub & 1) * 8;
                int acol = kk + (sub >> 1) * 8;
#pragma unroll
                for (int i = 0; i < 4; i++) {
                    int row = wm * 64 + i * 16 + arow;
                    ldsm4h(af[i], &As[row * SAH + acol]);
                }
            }
            if (BT) {
                int brow = rr + (sub & 1) * 8;
                int bcol = kk + (sub >> 1) * 8;
#pragma unroll
                for (int jp = 0; jp < 2; jp++) {
                    int n = wn * 32 + jp * 16 + brow;
                    unsigned tmp[4];
                    ldsm4h(tmp, &Bs[n * SAH + bcol]);
                    bf[jp * 2][0]     = tmp[0];
                    bf[jp * 2][1]     = tmp[2];
                    bf[jp * 2 + 1][0] = tmp[1];
                    bf[jp * 2 + 1][1] = tmp[3];
                }
            } else {
                int krow = kk + (sub & 1) * 8 + rr;
#pragma unroll
                for (int jp = 0; jp < 2; jp++) {
                    int ncol = wn * 32 + jp * 16 + (sub >> 1) * 8;
                    unsigned tmp[4];
                    ldsm4h_t(tmp, &Bs[krow * SBNH + ncol]);
                    bf[jp * 2][0]     = tmp[0];
                    bf[jp * 2][1]     = tmp[1];
                    bf[jp * 2 + 1][0] = tmp[2];
                    bf[jp * 2 + 1][1] = tmp[3];
                }
            }
#pragma unroll
            for (int i = 0; i < 4; i++)
#pragma unroll
                for (int j = 0; j < 4; j++)
                    mma_f16(acc[i][j], af[i], bf[j]);
        }
        __syncthreads();
    }

    // ---- epilogue (N exact multiple of BN; only M ragged) ----
#pragma unroll
    for (int i = 0; i < 4; i++) {
        int rm = m0 + wm * 64 + i * 16 + gid;
#pragma unroll
        for (int j = 0; j < 4; j++) {
            int cn = n0 + wn * 32 + j * 8 + tig * 2;
            if (rm < M) {
                epi.store(bh, rm, cn,     acc[i][j][0]);
                epi.store(bh, rm, cn + 1, acc[i][j][1]);
            }
            if (rm + 8 < M) {
                epi.store(bh, rm + 8, cn,     acc[i][j][2]);
                epi.store(bh, rm + 8, cn + 1, acc[i][j][3]);
            }
        }
    }
}

// ---------------------------------------------------------------------------
// Fused gauss + AV kernel (R15, unchanged).
// ---------------------------------------------------------------------------
#define FUSED_SMEM (2 * 128 * 72 * 2 + 128 * 136 * 2)   // Aq + Bs + Ps = 71680 B

template<class Out>
__global__ void __launch_bounds__(256)
fused_gauss_av(const __half* __restrict__ Abase,
               const __half* __restrict__ Bbase,
               const __half* __restrict__ Vbase,
               const float* __restrict__ xn, const float* __restrict__ yn,
               int nxs, int nys,
               size_t sA, size_t sB, size_t sV,
               int ntiles, Out out)
{
    constexpr int SAH = 72;
    constexpr int SPH = 136;
    extern __shared__ __half fsm[];
    __half* Aq = fsm;
    __half* Bs = Aq + 128 * SAH;
    __half* Ps = Bs + 128 * SAH;

    const int bh    = blockIdx.y;
    const int arow0 = blockIdx.x * 128;
    const int tid  = threadIdx.x;
    const int lane = tid & 31;
    const int warp = tid >> 5;
    const int wm = warp >> 2;
    const int wn = warp & 3;
    const int gid = lane >> 2;
    const int tig = lane & 3;
    const int rr  = lane & 7;
    const int sub = lane >> 3;

    const __half* Ag = Abase + (size_t)bh * sA + (size_t)arow0 * Dd;
    const __half* Bg = Bbase + (size_t)bh * sB;
    const __half* Vg = Vbase + (size_t)bh * sV;
    const float* xnb = xn + (size_t)bh * nxs + arow0;
    const float* ynb = yn + (size_t)bh * nys;

#pragma unroll
    for (int t = 0; t < 8; ++t) {
        int i = tid + t * 256;
        int r = i >> 4;
        int q = i & 15;
        *(uint2*)&Aq[r * SAH + q * 4] = *(const uint2*)&Ag[(size_t)r * Dd + q * 4];
    }

    float accY[4][2][4];
#pragma unroll
    for (int i = 0; i < 4; i++)
#pragma unroll
        for (int j = 0; j < 2; j++)
#pragma unroll
            for (int r = 0; r < 4; r++) accY[i][j][r] = 0.0f;

    for (int t = 0; t < ntiles; ++t) {
        __syncthreads();
#pragma unroll
        for (int u = 0; u < 8; ++u) {
            int i = tid + u * 256;
            int r = i >> 4, q = i & 15;
            *(uint2*)&Bs[r * SAH + q * 4] =
                *(const uint2*)&Bg[(size_t)(t * 128 + r) * Dd + q * 4];
        }
        __syncthreads();

#pragma unroll
        for (int nh = 0; nh < 2; ++nh) {
            float acc[4][2][4];
#pragma unroll
            for (int i = 0; i < 4; i++)
#pragma unroll
                for (int j = 0; j < 2; j++)
#pragma unroll
                    for (int r = 0; r < 4; r++) acc[i][j][r] = 0.0f;

#pragma unroll
            for (int kk = 0; kk < 64; kk += 16) {
                unsigned af[4][4], bf[2][2];
                int arow = rr + (sub & 1) * 8;
                int acol = kk + (sub >> 1) * 8;
#pragma unroll
                for (int i = 0; i < 4; i++)
                    ldsm4h(af[i], &Aq[(wm * 64 + i * 16 + arow) * SAH + acol]);
                int brow = nh * 64 + wn * 16 + rr + (sub & 1) * 8;
                int bcol = kk + (sub >> 1) * 8;
                unsigned tmp[4];
                ldsm4h(tmp, &Bs[brow * SAH + bcol]);
                bf[0][0] = tmp[0]; bf[0][1] = tmp[2];
                bf[1][0] = tmp[1]; bf[1][1] = tmp[3];
#pragma unroll
                for (int i = 0; i < 4; i++)
#pragma unroll
                    for (int j = 0; j < 2; j++)
                        mma_f16(acc[i][j], af[i], bf[j]);
            }
#pragma unroll
            for (int i = 0; i < 4; i++) {
                int rm = wm * 64 + i * 16 + gid;
                float xa = xnb[rm];
                float xb = xnb[rm + 8];
#pragma unroll
                for (int j = 0; j < 2; j++) {
                    int cn = nh * 64 + wn * 16 + j * 8 + tig * 2;
                    float y0 = ynb[t * 128 + cn];
                    float y1 = ynb[t * 128 + cn + 1];
                    float e0 = fast_exp((xa + y0 - 2.0f * acc[i][j][0]) * NEG_INV_TAU);
                    float e1 = fast_exp((xa + y1 - 2.0f * acc[i][j][1]) * NEG_INV_TAU);
                    float e2 = fast_exp((xb + y0 - 2.0f * acc[i][j][2]) * NEG_INV_TAU);
                    float e3 = fast_exp((xb + y1 - 2.0f * acc[i][j][3]) * NEG_INV_TAU);
                    *(__half2*)&Ps[rm * SPH + cn]       = __floats2half2_rn(e0, e1);
                    *(__half2*)&Ps[(rm + 8) * SPH + cn] = __floats2half2_rn(e2, e3);
                }
            }
        }
        __syncthreads();

#pragma unroll
        for (int u = 0; u < 8; ++u) {
            int i = tid + u * 256;
            int r = i >> 4, q = i & 15;
            *(uint2*)&Bs[r * SAH + q * 4] =
                *(const uint2*)&Vg[(size_t)(t * 128 + r) * Dd + q * 4];
        }
        __syncthreads();

#pragma unroll
        for (int kk = 0; kk < 128; kk += 16) {
            unsigned af[4][4], bf[2][2];
            int arow = rr + (sub & 1) * 8;
            int acol = kk + (sub >> 1) * 8;
#pragma unroll
            for (int i = 0; i < 4; i++)
                ldsm4h(af[i], &Ps[(wm * 64 + i * 16 + arow) * SPH + acol]);
            int krow = kk + (sub & 1) * 8 + rr;
            int ncol = wn * 16 + (sub >> 1) * 8;
            unsigned tmp[4];
            ldsm4h_t(tmp, &Bs[krow * SAH + ncol]);
            bf[0][0] = tmp[0]; bf[0][1] = tmp[1];
            bf[1][0] = tmp[2]; bf[1][1] = tmp[3];
#pragma unroll
            for (int i = 0; i < 4; i++)
#pragma unroll
                for (int j = 0; j < 2; j++)
                    mma_f16(accY[i][j], af[i], bf[j]);
        }
    }

#pragma unroll
    for (int i = 0; i < 4; i++) {
        int rm = wm * 64 + i * 16 + gid;
#pragma unroll
        for (int j = 0; j < 2; j++) {
            int cn = wn * 16 + j * 8 + tig * 2;
            out.store(bh, arow0 + rm,     cn,     accY[i][j][0]);
            out.store(bh, arow0 + rm,     cn + 1, accY[i][j][1]);
            out.store(bh, arow0 + rm + 8, cn,     accY[i][j][2]);
            out.store(bh, arow0 + rm + 8, cn + 1, accY[i][j][3]);
        }
    }
}

// ---------------------------------------------------------------------------
// Small helper kernels
// ---------------------------------------------------------------------------
__global__ void cvt_fp16_kernel(const float* __restrict__ src,
                                __half* __restrict__ dst, int n)
{
    int i = (blockIdx.x * blockDim.x + threadIdx.x) * 4;
    if (i >= n) return;
    float4 v = *(const float4*)&src[i];
    uint2 u = make_uint2(pack2h(v.x, v.y), pack2h(v.z, v.w));
    *(uint2*)&dst[i] = u;
}

__global__ void pool_kernel()
{
    int idx = blockIdx.x * blockDim.x + threadIdx.x;
    if (idx >= BH * Ll * Dd) return;
    int d  = idx % Dd;
    int l  = (idx / Dd) % Ll;
    int bh = idx / (Dd * Ll);
    int lr = l / 16, lc = l % 16;
    float sq = 0.f, sk = 0.f;
#pragma unroll
    for (int r = 0; r < 2; r++)
#pragma unroll
        for (int c = 0; c < 2; c++) {
            int p = (2 * lr + r) * 32 + (2 * lc + c);
            size_t off = ((size_t)bh * NT + (p + 1)) * Dd + d;
            sq += __half2float(g_q[off]);
            sk += __half2float(g_k[off]);
        }
    g_qland[((size_t)bh * Ll + l) * Dd + d] = __float2half_rn(sq * 0.25f);
    g_kland[((size_t)bh * Ll + l) * Dd + d] = __float2half_rn(sk * 0.25f);
}

__device__ __forceinline__ float row_sq_norm_h(const __half* p)
{
    const __half2* p2 = (const __half2*)p;
    float s = 0.f;
#pragma unroll
    for (int i = 0; i < Dd / 2; i++) {
        float2 v = __half22float2(p2[i]);
        s += v.x * v.x + v.y * v.y;
    }
    return s;
}

__global__ void norms_patch_kernel()
{
    int idx = blockIdx.x * blockDim.x + threadIdx.x;
    if (idx >= BH * NP) return;
    int bh = idx / NP, p = idx % NP;
    size_t off = ((size_t)bh * NT + (p + 1)) * Dd;
    g_qpn[idx] = row_sq_norm_h(&g_q[off]);
    g_kpn[idx] = row_sq_norm_h(&g_k[off]);
}

__global__ void norms_land_kernel()
{
    int idx = blockIdx.x * blockDim.x + threadIdx.x;
    if (idx >= BH * Ll) return;
    g_qln[idx] = row_sq_norm_h(&g_qland[(size_t)idx * Dd]);
    g_kln[idx] = row_sq_norm_h(&g_kland[(size_t)idx * Dd]);
    if (idx < BH)
        g_qcn[idx] = row_sq_norm_h(&g_q[(size_t)idx * NT * Dd]);  // n = 0 (cls)
}

__global__ void newton_init_kernel()
{
    int bh = blockIdx.x;
    int t  = threadIdx.x;
    const __half* M2b = g_M2 + (size_t)bh * Ll * Ll;
    const __half* row = M2b + (size_t)t * Ll;
    float rs = 0.f;
    for (int j = 0; j < Ll; j++) rs += fabsf(__half2float(row[j]));
    __shared__ float red[256];
    red[t] = rs;
    __syncthreads();
    for (int s = 128; s > 0; s >>= 1) {
        if (t < s) red[t] = fmaxf(red[t], red[t + s]);
        __syncthreads();
    }
    float nrm = red[0];
    float scale = 1.0f / (nrm * nrm + 1e-6f);
    __half* inv = g_invA + (size_t)bh * Ll * Ll;
    for (int idx = t; idx < Ll * Ll; idx += 256) {
        int i = idx / Ll, j = idx % Ll;
        inv[idx] = __float2half_rn(__half2float(M2b[(size_t)j * Ll + i]) * scale);
    }
}

__global__ void ycls_kernel()
{
    int bh = blockIdx.x;
    int t  = threadIdx.x;
    __shared__ float sc[Ll];
    __shared__ float qc[Dd];
    if (t < Dd) qc[t] = __half2float(g_q[(size_t)bh * NT * Dd + t]);
    __syncthreads();
    const __half* kl = g_kland + ((size_t)bh * Ll + t) * Dd;
    float dot = 0.f;
#pragma unroll
    for (int d = 0; d < Dd; d++) dot += qc[d] * __half2float(kl[d]);
    float dist = g_qcn[bh] + g_kln[(size_t)bh * Ll + t] - 2.0f * dot;
    sc[t] = fast_exp(dist * NEG_INV_TAU);
    __syncthreads();
    if (t < Dd) {
        float s = 0.f;
        for (int l = 0; l < Ll; l++)
            s += sc[l] * __half2float(g_Vmix[((size_t)bh * Ll + l) * Dd + t]);
        int b = bh / Hh, h = bh % Hh;
        g_attn[(size_t)b * NT * Cd + h * Dd + t] = __float2half_rn(s);
    }
}

// ---------------------------------------------------------------------------
// Host launchers
// ---------------------------------------------------------------------------
template<int BM, int BN, bool BT, class Epi>
static void launch_gemm(dim3 grid, const __half* A, const __half* Bp,
                        int M, int Nn, int K, int lda, int ldb,
                        size_t sA, size_t sB, Epi epi)
{
    constexpr int THREADS = (BM / 64) * (BN / 32) * 32;
    gemm_tc<BM, BN, BT, Epi><<<grid, THREADS>>>(
        A, Bp, M, Nn, K, lda, ldb, sA, sB, epi);
}

template<class Out>
static void launch_fused(dim3 grid, const __half* A, const __half* B, const __half* V,
                         const float* xn, const float* yn, int nxs, int nys,
                         size_t sA, size_t sB, size_t sV, int ntiles, Out out)
{
    static bool attr_done = false;
    if (!attr_done) {
        cudaFuncSetAttribute((const void*)fused_gauss_av<Out>,
                             cudaFuncAttributeMaxDynamicSharedMemorySize, FUSED_SMEM);
        attr_done = true;
    }
    fused_gauss_av<Out><<<grid, 256, FUSED_SMEM>>>(
        A, B, V, xn, yn, nxs, nys, sA, sB, sV, ntiles, out);
}

extern "C" void kernel_launch(void* const* d_in, const int* in_sizes, int n_in,
                              void* d_out, int out_size)
{
    (void)in_sizes; (void)n_in; (void)out_size;
    const float* x      = (const float*)d_in[0];
    const float* qkv_w  = (const float*)d_in[1];
    const float* qkv_b  = (const float*)d_in[2];
    const float* proj_w = (const float*)d_in[3];
    const float* proj_b = (const float*)d_in[4];
    float* out = (float*)d_out;

    __half *p_xh, *p_qkvwh, *p_projwh;
    __half *p_q, *p_k, *p_v, *p_qland, *p_kland;
    float *p_qpn, *p_kpn, *p_qln, *p_kln;
    __half *p_M2, *p_invA, *p_invB, *p_T, *p_KV, *p_Vmix, *p_attn;
    cudaGetSymbolAddress((void**)&p_xh, g_xh);
    cudaGetSymbolAddress((void**)&p_qkvwh, g_qkvwh);
    cudaGetSymbolAddress((void**)&p_projwh, g_projwh);
    cudaGetSymbolAddress((void**)&p_q, g_q);
    cudaGetSymbolAddress((void**)&p_k, g_k);
    cudaGetSymbolAddress((void**)&p_v, g_v);
    cudaGetSymbolAddress((void**)&p_qland, g_qland);
    cudaGetSymbolAddress((void**)&p_kland, g_kland);
    cudaGetSymbolAddress((void**)&p_qpn, g_qpn);
    cudaGetSymbolAddress((void**)&p_kpn, g_kpn);
    cudaGetSymbolAddress((void**)&p_qln, g_qln);
    cudaGetSymbolAddress((void**)&p_kln, g_kln);
    cudaGetSymbolAddress((void**)&p_M2, g_M2);
    cudaGetSymbolAddress((void**)&p_invA, g_invA);
    cudaGetSymbolAddress((void**)&p_invB, g_invB);
    cudaGetSymbolAddress((void**)&p_T, g_T);
    cudaGetSymbolAddress((void**)&p_KV, g_KV);
    cudaGetSymbolAddress((void**)&p_Vmix, g_Vmix);
    cudaGetSymbolAddress((void**)&p_attn, g_attn);

    const int M_tok = Bn * NT;   // 16400
    const int gy_tok = (M_tok + 127) / 128;

    // 0. pre-convert fp32 inputs to fp16
    {
        int nx = Bn * NT * Cd;          // 12,595,200
        int nw = 3 * Cd * Cd;           // 1,769,472
        int np = Cd * Cd;               // 589,824
        cvt_fp16_kernel<<<(nx / 4 + 255) / 256, 256>>>(x, p_xh, nx);
        cvt_fp16_kernel<<<(nw / 4 + 255) / 256, 256>>>(qkv_w, p_qkvwh, nw);
        cvt_fp16_kernel<<<(np / 4 + 255) / 256, 256>>>(proj_w, p_projwh, np);
    }

    // 1. QKV projection (fp16 x @ fp16 w^T)
    launch_gemm<128, 128, true>(dim3(3 * Cd / 128, gy_tok, 1),
        p_xh, p_qkvwh, M_tok, 3 * Cd, Cd, Cd, Cd, (size_t)0, (size_t)0,
        EpiQKV{qkv_b});

    // 2. pooling + norms
    pool_kernel<<<(BH * Ll * Dd + 255) / 256, 256>>>();
    norms_patch_kernel<<<(BH * NP + 255) / 256, 256>>>();
    norms_land_kernel<<<(BH * Ll + 255) / 256, 256>>>();

    // 3. M2 gauss (needed for Newton)
    launch_gemm<128, 128, true>(dim3(Ll / 128, Ll / 128, BH),
        p_qland, p_kland, Ll, Ll, Dd, Dd, Dd,
        (size_t)Ll * Dd, (size_t)Ll * Dd,
        EpiGauss{p_qln, p_kln, p_M2, Ll, Ll, Ll, (size_t)Ll * Ll});

    // 4. fused M3+KV: KV = gauss(q_land, k_patch) @ v_patch
    launch_fused(dim3(2, BH), p_qland, p_k + Dd, p_v + Dd,
                 p_qln, p_kpn, Ll, NP,
                 (size_t)Ll * Dd, (size_t)NT * Dd, (size_t)NT * Dd, NP / 128, OutKV{});

    // 5. Newton iterations for M2^-1
    newton_init_kernel<<<BH, 256>>>();
    {
        __half* cur = p_invA;
        __half* nxt = p_invB;
        dim3 grid(Ll / 128, Ll / 128, BH);
        for (int it = 0; it < NEWTON_ITERS; it++) {
            launch_gemm<128, 128, false>(grid,
                p_M2, (const __half*)cur, Ll, Ll, Ll, Ll, Ll,
                (size_t)Ll * Ll, (size_t)Ll * Ll,
                EpiPlainH{p_T, Ll, (size_t)Ll * Ll});
            launch_gemm<128, 128, false>(grid,
                (const __half*)cur, p_T, Ll, Ll, Ll, Ll, Ll,
                (size_t)Ll * Ll, (size_t)Ll * Ll,
                EpiNewton{cur, nxt});
            __half* tmp = cur; cur = nxt; nxt = tmp;
        }
        // NEWTON_ITERS even -> result in p_invA
    }

    // 6. V_mixed = M2_inv @ KV : [L x D]
    launch_gemm<128, 64, false>(dim3(1, Ll / 128, BH),
        (const __half*)p_invA, p_KV, Ll, Dd, Ll, Ll, Dd,
        (size_t)Ll * Ll, (size_t)Ll * Dd,
        EpiPlainH{p_Vmix, Dd, (size_t)Ll * Dd});

    // 7. fused M1+y_patch: attn_patch = gauss(q_patch, k_land) @ V_mixed
    launch_fused(dim3(NP / 128, BH), p_q + Dd, p_kland, p_Vmix,
                 p_qpn, p_kln, NP, Ll,
                 (size_t)NT * Dd, (size_t)Ll * Dd, (size_t)Ll * Dd, Ll / 128, OutYP{});

    // 8. y_cls
    ycls_kernel<<<BH, 256>>>();

    // 9. output projection (fp16 attn @ fp16 w^T, fp32 out)
    launch_gemm<128, 128, true>(dim3(Cd / 128, gy_tok, 1),
        (const __half*)p_attn, p_projwh, M_tok, Cd, Cd, Cd, Cd,
        (size_t)0, (size_t)0, EpiProj{proj_b, out});
}